// round 2
// baseline (speedup 1.0000x reference)
#include <cuda_runtime.h>
#include <cuda_bf16.h>
#include <math.h>

#define N_TOK   4096
#define D_MODEL 1024
#define N_HEADS 16
#define HD      64
#define KV_DIM  2048

// ---------------- scratch (device globals; no allocation allowed) ----------
__device__ float g_x [N_TOK * D_MODEL];   // layernorm output
__device__ float g_qp[N_TOK * D_MODEL];   // q projection  [n, h*64+d]
__device__ float g_kv[N_TOK * KV_DIM];    // kv projection [n, 2048]
__device__ float g_ao[N_TOK * D_MODEL];   // attention output [n, h*64+d]

// ---------------------------------------------------------------------------
// LayerNorm: one block per row (1024 elems), 256 threads, float4 per thread
// ---------------------------------------------------------------------------
__device__ __forceinline__ float block_allreduce(float v) {
    __shared__ float red[8];
    __shared__ float bc;
    #pragma unroll
    for (int m = 16; m >= 1; m >>= 1) v += __shfl_xor_sync(0xffffffffu, v, m);
    if ((threadIdx.x & 31) == 0) red[threadIdx.x >> 5] = v;
    __syncthreads();
    if (threadIdx.x == 0) {
        float t = 0.f;
        #pragma unroll
        for (int i = 0; i < 8; i++) t += red[i];
        bc = t;
    }
    __syncthreads();
    float r = bc;
    __syncthreads();   // make red/bc reusable for a second call
    return r;
}

__global__ __launch_bounds__(256) void ln_kernel(
    const float* __restrict__ q, const float* __restrict__ gamma,
    const float* __restrict__ beta, float* __restrict__ x)
{
    int row = blockIdx.x;
    int tid = threadIdx.x;
    const float4 v = ((const float4*)(q + (size_t)row * D_MODEL))[tid];

    float s = v.x + v.y + v.z + v.w;
    float total = block_allreduce(s);
    float mu = total * (1.0f / D_MODEL);

    float dx = v.x - mu, dy = v.y - mu, dz = v.z - mu, dw = v.w - mu;
    float sq = dx*dx + dy*dy + dz*dz + dw*dw;
    float var = block_allreduce(sq) * (1.0f / D_MODEL);
    float rstd = rsqrtf(var + 1e-5f);

    const float4 g = ((const float4*)gamma)[tid];
    const float4 b = ((const float4*)beta)[tid];
    float4 o;
    o.x = dx * rstd * g.x + b.x;
    o.y = dy * rstd * g.y + b.y;
    o.z = dz * rstd * g.z + b.z;
    o.w = dw * rstd * g.w + b.w;
    ((float4*)(x + (size_t)row * D_MODEL))[tid] = o;
}

// ---------------------------------------------------------------------------
// GEMM: C[M,N] = A[M,K] @ B[N,K]^T   (fp32, 128x128x16 tile, 8x8/thread)
// ---------------------------------------------------------------------------
__global__ __launch_bounds__(256) void gemm_nt_kernel(
    const float* __restrict__ A, const float* __restrict__ B,
    float* __restrict__ C, int M, int N, int K)
{
    __shared__ float As[16][132];  // [k][m], padded
    __shared__ float Bs[16][132];  // [k][n], padded

    int tid = threadIdx.x;
    int tx = tid & 15;        // 0..15 -> N sub-block
    int ty = tid >> 4;        // 0..15 -> M sub-block
    int brow = blockIdx.y * 128;
    int bcol = blockIdx.x * 128;

    float acc[8][8];
    #pragma unroll
    for (int i = 0; i < 8; i++)
        #pragma unroll
        for (int j = 0; j < 8; j++) acc[i][j] = 0.f;

    for (int k0 = 0; k0 < K; k0 += 16) {
        // load tiles: 128x16 floats each = 512 float4, 2 per thread per matrix
        #pragma unroll
        for (int r = 0; r < 2; r++) {
            int f   = tid + 256 * r;
            int row = f >> 2;
            int c4  = (f & 3) * 4;
            float4 va = *(const float4*)&A[(size_t)(brow + row) * K + k0 + c4];
            As[c4+0][row] = va.x; As[c4+1][row] = va.y;
            As[c4+2][row] = va.z; As[c4+3][row] = va.w;
            float4 vb = *(const float4*)&B[(size_t)(bcol + row) * K + k0 + c4];
            Bs[c4+0][row] = vb.x; Bs[c4+1][row] = vb.y;
            Bs[c4+2][row] = vb.z; Bs[c4+3][row] = vb.w;
        }
        __syncthreads();

        #pragma unroll
        for (int kk = 0; kk < 16; kk++) {
            float a[8], b[8];
            *(float4*)&a[0] = *(const float4*)&As[kk][ty*8];
            *(float4*)&a[4] = *(const float4*)&As[kk][ty*8+4];
            *(float4*)&b[0] = *(const float4*)&Bs[kk][tx*8];
            *(float4*)&b[4] = *(const float4*)&Bs[kk][tx*8+4];
            #pragma unroll
            for (int i = 0; i < 8; i++)
                #pragma unroll
                for (int j = 0; j < 8; j++)
                    acc[i][j] = fmaf(a[i], b[j], acc[i][j]);
        }
        __syncthreads();
    }

    #pragma unroll
    for (int i = 0; i < 8; i++) {
        float4* cp = (float4*)&C[(size_t)(brow + ty*8 + i) * N + bcol + tx*8];
        cp[0] = make_float4(acc[i][0], acc[i][1], acc[i][2], acc[i][3]);
        cp[1] = make_float4(acc[i][4], acc[i][5], acc[i][6], acc[i][7]);
    }
}

// ---------------------------------------------------------------------------
// Flash attention (fp32): block = 256 threads = 16x16, 64 queries of one head.
// Streams 64-key tiles, online softmax, 4x4 S and 4x4 O fragments per thread.
// smem layout (dynamic):
//   Qt[d][q] 64x68, Kt[d][k] 64x68, Vs[k][d] 64x68, Pt[k][q] 64x68
// ---------------------------------------------------------------------------
#define AP 68
#define ATTN_SMEM (4 * 64 * AP * 4)

__global__ __launch_bounds__(256) void attn_kernel(
    const float* __restrict__ qp, const float* __restrict__ kv,
    float* __restrict__ ao)
{
    extern __shared__ float smem[];
    float* Qt = smem;              // [64][AP]  (d-major)
    float* Kt = Qt + 64 * AP;      // [64][AP]  (d-major)
    float* Vs = Kt + 64 * AP;      // [64][AP]  (k-major)
    float* Pt = Vs + 64 * AP;      // [64][AP]  (k-major)

    const int tid = threadIdx.x;
    const int tx = tid & 15;       // key/dim sub-block
    const int ty = tid >> 4;       // query sub-block
    const int qbase = blockIdx.x * 64;
    const int hbase = blockIdx.y * HD;
    const float scale = 0.125f;    // 1/sqrt(64)

    // Load Q tile transposed (scaled): 64 q x 64 d
    #pragma unroll
    for (int r = 0; r < 4; r++) {
        int e  = tid + 256 * r;
        int ql = e >> 4;
        int d4 = (e & 15) * 4;
        float4 v = *(const float4*)&qp[(size_t)(qbase + ql) * D_MODEL + hbase + d4];
        Qt[(d4+0)*AP + ql] = v.x * scale;
        Qt[(d4+1)*AP + ql] = v.y * scale;
        Qt[(d4+2)*AP + ql] = v.z * scale;
        Qt[(d4+3)*AP + ql] = v.w * scale;
    }

    float m[4], l[4], acc[4][4];
    #pragma unroll
    for (int i = 0; i < 4; i++) {
        m[i] = -1e30f; l[i] = 0.f;
        #pragma unroll
        for (int j = 0; j < 4; j++) acc[i][j] = 0.f;
    }
    __syncthreads();

    for (int t = 0; t < N_TOK / 64; t++) {
        // load K tile (transposed) and V tile
        #pragma unroll
        for (int r = 0; r < 4; r++) {
            int e  = tid + 256 * r;
            int kl = e >> 4;
            int d4 = (e & 15) * 4;
            const size_t grow = (size_t)(t * 64 + kl) * KV_DIM;
            float4 kvec = *(const float4*)&kv[grow + hbase + d4];
            Kt[(d4+0)*AP + kl] = kvec.x;
            Kt[(d4+1)*AP + kl] = kvec.y;
            Kt[(d4+2)*AP + kl] = kvec.z;
            Kt[(d4+3)*AP + kl] = kvec.w;
            float4 vvec = *(const float4*)&kv[grow + D_MODEL + hbase + d4];
            *(float4*)&Vs[kl*AP + d4] = vvec;
        }
        __syncthreads();

        // S = Q K^T  (4x4 per thread)
        float s[4][4];
        #pragma unroll
        for (int i = 0; i < 4; i++)
            #pragma unroll
            for (int j = 0; j < 4; j++) s[i][j] = 0.f;

        #pragma unroll 16
        for (int d = 0; d < 64; d++) {
            float4 a = *(const float4*)&Qt[d*AP + ty*4];
            float4 b = *(const float4*)&Kt[d*AP + tx*4];
            float av[4] = {a.x, a.y, a.z, a.w};
            float bv[4] = {b.x, b.y, b.z, b.w};
            #pragma unroll
            for (int i = 0; i < 4; i++)
                #pragma unroll
                for (int j = 0; j < 4; j++)
                    s[i][j] = fmaf(av[i], bv[j], s[i][j]);
        }

        // online softmax per query row (rows spread over 16 lanes sharing ty)
        #pragma unroll
        for (int i = 0; i < 4; i++) {
            float rmax = fmaxf(fmaxf(s[i][0], s[i][1]), fmaxf(s[i][2], s[i][3]));
            #pragma unroll
            for (int msk = 8; msk >= 1; msk >>= 1)
                rmax = fmaxf(rmax, __shfl_xor_sync(0xffffffffu, rmax, msk));
            float mnew = fmaxf(m[i], rmax);
            float corr = __expf(m[i] - mnew);
            float ls = 0.f;
            #pragma unroll
            for (int j = 0; j < 4; j++) {
                float p = __expf(s[i][j] - mnew);
                Pt[(tx*4+j)*AP + ty*4 + i] = p;
                ls += p;
            }
            #pragma unroll
            for (int msk = 8; msk >= 1; msk >>= 1)
                ls += __shfl_xor_sync(0xffffffffu, ls, msk);
            l[i] = l[i] * corr + ls;
            m[i] = mnew;
            #pragma unroll
            for (int j = 0; j < 4; j++) acc[i][j] *= corr;
        }
        __syncthreads();

        // O += P V  (4x4 per thread; dims tx*4..+3)
        #pragma unroll 16
        for (int k = 0; k < 64; k++) {
            float4 p = *(const float4*)&Pt[k*AP + ty*4];
            float4 v = *(const float4*)&Vs[k*AP + tx*4];
            float pv[4] = {p.x, p.y, p.z, p.w};
            float vv[4] = {v.x, v.y, v.z, v.w};
            #pragma unroll
            for (int i = 0; i < 4; i++)
                #pragma unroll
                for (int j = 0; j < 4; j++)
                    acc[i][j] = fmaf(pv[i], vv[j], acc[i][j]);
        }
        __syncthreads();
    }

    #pragma unroll
    for (int i = 0; i < 4; i++) {
        float inv = 1.0f / l[i];
        float4 o = make_float4(acc[i][0]*inv, acc[i][1]*inv,
                               acc[i][2]*inv, acc[i][3]*inv);
        *(float4*)&ao[(size_t)(qbase + ty*4 + i) * D_MODEL + hbase + tx*4] = o;
    }
}

// ---------------------------------------------------------------------------
extern "C" void kernel_launch(void* const* d_in, const int* in_sizes, int n_in,
                              void* d_out, int out_size)
{
    (void)in_sizes; (void)n_in; (void)out_size;
    const float* q     = (const float*)d_in[0];
    const float* gamma = (const float*)d_in[1];
    const float* beta  = (const float*)d_in[2];
    const float* Wq    = (const float*)d_in[3];
    const float* Wkv   = (const float*)d_in[4];
    const float* Wo    = (const float*)d_in[5];
    float* out = (float*)d_out;

    float *x, *qp, *kvb, *ao;
    cudaGetSymbolAddress((void**)&x,   g_x);
    cudaGetSymbolAddress((void**)&qp,  g_qp);
    cudaGetSymbolAddress((void**)&kvb, g_kv);
    cudaGetSymbolAddress((void**)&ao,  g_ao);

    cudaFuncSetAttribute(attn_kernel, cudaFuncAttributeMaxDynamicSharedMemorySize, ATTN_SMEM);

    ln_kernel<<<N_TOK, 256>>>(q, gamma, beta, x);

    gemm_nt_kernel<<<dim3(D_MODEL/128, N_TOK/128), 256>>>(x, Wq,  qp,  N_TOK, D_MODEL, D_MODEL);
    gemm_nt_kernel<<<dim3(KV_DIM/128,  N_TOK/128), 256>>>(x, Wkv, kvb, N_TOK, KV_DIM,  D_MODEL);

    attn_kernel<<<dim3(N_TOK/64, N_HEADS), 256, ATTN_SMEM>>>(qp, kvb, ao);

    gemm_nt_kernel<<<dim3(D_MODEL/128, N_TOK/128), 256>>>(ao, Wo, out, N_TOK, D_MODEL, D_MODEL);
}

// round 4
// speedup vs baseline: 1.9001x; 1.9001x over previous
#include <cuda_runtime.h>
#include <stdint.h>
#include <math.h>

#define N_TOK   4096
#define D_MODEL 1024
#define N_HEADS 16
#define HD      64
#define KV_DIM  2048

// ---------------- scratch (device globals; no allocation allowed) ----------
__device__ float g_x [N_TOK * D_MODEL];   // layernorm output
__device__ float g_qp[N_TOK * D_MODEL];   // q projection  [n, h*64+d]
__device__ float g_kv[N_TOK * KV_DIM];    // kv projection [n, 2048]
__device__ float g_ao[N_TOK * D_MODEL];   // attention output [n, h*64+d]

// ---------------------------------------------------------------------------
// helpers
// ---------------------------------------------------------------------------
__device__ __forceinline__ uint32_t f2tf32(float f) {
    uint32_t r;
    asm("cvt.rna.tf32.f32 %0, %1;" : "=r"(r) : "f"(f));
    return r;
}

__device__ __forceinline__ void mma_tf32(float c[4], const uint32_t a[4], const uint32_t b[2]) {
    asm volatile(
        "mma.sync.aligned.m16n8k8.row.col.f32.tf32.tf32.f32 "
        "{%0,%1,%2,%3}, {%4,%5,%6,%7}, {%8,%9}, {%0,%1,%2,%3};"
        : "+f"(c[0]), "+f"(c[1]), "+f"(c[2]), "+f"(c[3])
        : "r"(a[0]), "r"(a[1]), "r"(a[2]), "r"(a[3]), "r"(b[0]), "r"(b[1]));
}

// ---------------------------------------------------------------------------
// LayerNorm: one block per row (1024 elems), 256 threads, float4 per thread
// ---------------------------------------------------------------------------
__device__ __forceinline__ float block_allreduce(float v) {
    __shared__ float red[8];
    __shared__ float bc;
    #pragma unroll
    for (int m = 16; m >= 1; m >>= 1) v += __shfl_xor_sync(0xffffffffu, v, m);
    if ((threadIdx.x & 31) == 0) red[threadIdx.x >> 5] = v;
    __syncthreads();
    if (threadIdx.x == 0) {
        float t = 0.f;
        #pragma unroll
        for (int i = 0; i < 8; i++) t += red[i];
        bc = t;
    }
    __syncthreads();
    float r = bc;
    __syncthreads();
    return r;
}

__global__ __launch_bounds__(256) void ln_kernel(
    const float* __restrict__ q, const float* __restrict__ gamma,
    const float* __restrict__ beta, float* __restrict__ x)
{
    int row = blockIdx.x;
    int tid = threadIdx.x;
    const float4 v = ((const float4*)(q + (size_t)row * D_MODEL))[tid];

    float s = v.x + v.y + v.z + v.w;
    float mu = block_allreduce(s) * (1.0f / D_MODEL);

    float dx = v.x - mu, dy = v.y - mu, dz = v.z - mu, dw = v.w - mu;
    float var = block_allreduce(dx*dx + dy*dy + dz*dz + dw*dw) * (1.0f / D_MODEL);
    float rstd = rsqrtf(var + 1e-5f);

    const float4 g = ((const float4*)gamma)[tid];
    const float4 b = ((const float4*)beta)[tid];
    float4 o;
    o.x = dx * rstd * g.x + b.x;
    o.y = dy * rstd * g.y + b.y;
    o.z = dz * rstd * g.z + b.z;
    o.w = dw * rstd * g.w + b.w;
    ((float4*)(x + (size_t)row * D_MODEL))[tid] = o;
}

// ---------------------------------------------------------------------------
// GEMM (3xTF32): C[M,N] = A[M,K] @ B[N,K]^T
// 128x128 block tile, 16 K-tile, 8 warps (4x2), warp tile 32x64.
// smem layouts [row][k] with stride 20 (==4 mod 32 -> conflict-free frags).
// ---------------------------------------------------------------------------
#define GS 20

__global__ __launch_bounds__(256) void gemm_tf32x3_kernel(
    const float* __restrict__ A, const float* __restrict__ B,
    float* __restrict__ C, int M, int N, int K)
{
    __shared__ uint32_t Ah[128 * GS], Al[128 * GS];
    __shared__ uint32_t Bh[128 * GS], Bl[128 * GS];

    const int tid  = threadIdx.x;
    const int lane = tid & 31;
    const int warp = tid >> 5;
    const int wm   = (warp >> 1) * 32;   // warp M offset (4 warps)
    const int wn   = (warp & 1) * 64;    // warp N offset (2 warps)
    const int g    = lane >> 2;
    const int q    = lane & 3;
    const int brow = blockIdx.y * 128;
    const int bcol = blockIdx.x * 128;

    float acc[2][8][4];
    #pragma unroll
    for (int mt = 0; mt < 2; mt++)
        #pragma unroll
        for (int nt = 0; nt < 8; nt++)
            #pragma unroll
            for (int i = 0; i < 4; i++) acc[mt][nt][i] = 0.f;

    for (int k0 = 0; k0 < K; k0 += 16) {
        __syncthreads();
        #pragma unroll
        for (int r = 0; r < 2; r++) {
            int f   = tid + 256 * r;
            int row = f >> 2;
            int c4  = (f & 3) * 4;
            float4 va = *(const float4*)&A[(size_t)(brow + row) * K + k0 + c4];
            float4 vb = *(const float4*)&B[(size_t)(bcol + row) * K + k0 + c4];
            float av[4] = {va.x, va.y, va.z, va.w};
            float bv[4] = {vb.x, vb.y, vb.z, vb.w};
            #pragma unroll
            for (int j = 0; j < 4; j++) {
                uint32_t h = f2tf32(av[j]);
                Ah[row * GS + c4 + j] = h;
                Al[row * GS + c4 + j] = f2tf32(av[j] - __uint_as_float(h));
                h = f2tf32(bv[j]);
                Bh[row * GS + c4 + j] = h;
                Bl[row * GS + c4 + j] = f2tf32(bv[j] - __uint_as_float(h));
            }
        }
        __syncthreads();

        #pragma unroll
        for (int kb = 0; kb < 16; kb += 8) {
            uint32_t ah[2][4], al[2][4], bh[8][2], bl[8][2];
            #pragma unroll
            for (int mt = 0; mt < 2; mt++) {
                int r0 = wm + mt * 16 + g;
                ah[mt][0] = Ah[r0       * GS + kb + q];
                ah[mt][1] = Ah[(r0 + 8) * GS + kb + q];
                ah[mt][2] = Ah[r0       * GS + kb + q + 4];
                ah[mt][3] = Ah[(r0 + 8) * GS + kb + q + 4];
                al[mt][0] = Al[r0       * GS + kb + q];
                al[mt][1] = Al[(r0 + 8) * GS + kb + q];
                al[mt][2] = Al[r0       * GS + kb + q + 4];
                al[mt][3] = Al[(r0 + 8) * GS + kb + q + 4];
            }
            #pragma unroll
            for (int nt = 0; nt < 8; nt++) {
                int n0 = wn + nt * 8 + g;
                bh[nt][0] = Bh[n0 * GS + kb + q];
                bh[nt][1] = Bh[n0 * GS + kb + q + 4];
                bl[nt][0] = Bl[n0 * GS + kb + q];
                bl[nt][1] = Bl[n0 * GS + kb + q + 4];
            }
            #pragma unroll
            for (int mt = 0; mt < 2; mt++)
                #pragma unroll
                for (int nt = 0; nt < 8; nt++)
                    mma_tf32(acc[mt][nt], ah[mt], bh[nt]);
            #pragma unroll
            for (int mt = 0; mt < 2; mt++)
                #pragma unroll
                for (int nt = 0; nt < 8; nt++)
                    mma_tf32(acc[mt][nt], al[mt], bh[nt]);
            #pragma unroll
            for (int mt = 0; mt < 2; mt++)
                #pragma unroll
                for (int nt = 0; nt < 8; nt++)
                    mma_tf32(acc[mt][nt], ah[mt], bl[nt]);
        }
    }

    #pragma unroll
    for (int mt = 0; mt < 2; mt++) {
        int r0 = brow + wm + mt * 16 + g;
        #pragma unroll
        for (int nt = 0; nt < 8; nt++) {
            int cc = bcol + wn + nt * 8 + 2 * q;
            *(float2*)&C[(size_t)r0 * N + cc]       = make_float2(acc[mt][nt][0], acc[mt][nt][1]);
            *(float2*)&C[(size_t)(r0 + 8) * N + cc] = make_float2(acc[mt][nt][2], acc[mt][nt][3]);
        }
    }
}

// ---------------------------------------------------------------------------
// Flash attention with tf32 mma: block = 256 thr (8 warps), 128 queries/head.
// Warp w owns query rows 16w..16w+15. KV tiles of 64 keys.
// smem (uint32 words): Ps[128][68] (Q stage, then P), Ks[64][68], Vs[64][72].
// ---------------------------------------------------------------------------
#define QS 68
#define KSD 68
#define VSD 72
#define ATTN_SMEM_BYTES ((128 * QS + 64 * KSD + 64 * VSD) * 4)

__global__ __launch_bounds__(256) void attn_tf32_kernel(
    const float* __restrict__ qp, const float* __restrict__ kv,
    float* __restrict__ ao)
{
    extern __shared__ uint32_t sm[];
    uint32_t* Ps = sm;                 // [128][QS]
    uint32_t* Ks = sm + 128 * QS;      // [64][KSD]  (key-major: [key][dim])
    uint32_t* Vs = Ks + 64 * KSD;      // [64][VSD]  (key-major: [key][dim])

    const int tid   = threadIdx.x;
    const int lane  = tid & 31;
    const int warp  = tid >> 5;
    const int g     = lane >> 2;
    const int q     = lane & 3;
    const int qbase = blockIdx.x * 128;
    const int hbase = blockIdx.y * HD;
    const int r0    = warp * 16 + g;   // this thread's first query row (local)

    // ---- stage Q (scaled by 1/8) as tf32 into Ps ----
    #pragma unroll
    for (int r = 0; r < 8; r++) {
        int e   = tid + 256 * r;
        int row = e >> 4;
        int d4  = (e & 15) * 4;
        float4 v = *(const float4*)&qp[(size_t)(qbase + row) * D_MODEL + hbase + d4];
        Ps[row * QS + d4 + 0] = f2tf32(v.x * 0.125f);
        Ps[row * QS + d4 + 1] = f2tf32(v.y * 0.125f);
        Ps[row * QS + d4 + 2] = f2tf32(v.z * 0.125f);
        Ps[row * QS + d4 + 3] = f2tf32(v.w * 0.125f);
    }
    __syncthreads();

    // ---- preload Q fragments (reused for all KV tiles) ----
    uint32_t qf[8][4];
    #pragma unroll
    for (int kb = 0; kb < 8; kb++) {
        qf[kb][0] = Ps[r0       * QS + kb * 8 + q];
        qf[kb][1] = Ps[(r0 + 8) * QS + kb * 8 + q];
        qf[kb][2] = Ps[r0       * QS + kb * 8 + q + 4];
        qf[kb][3] = Ps[(r0 + 8) * QS + kb * 8 + q + 4];
    }

    float o[8][4];
    #pragma unroll
    for (int nt = 0; nt < 8; nt++)
        #pragma unroll
        for (int i = 0; i < 4; i++) o[nt][i] = 0.f;
    float mrow0 = -1e30f, mrow1 = -1e30f, lrow0 = 0.f, lrow1 = 0.f;

    for (int t = 0; t < N_TOK / 64; t++) {
        __syncthreads();   // everyone done reading previous K/V (and Q->frags on t=0)
        #pragma unroll
        for (int r = 0; r < 4; r++) {
            int e   = tid + 256 * r;
            int key = e >> 4;
            int d4  = (e & 15) * 4;
            size_t gr = (size_t)(t * 64 + key) * KV_DIM + hbase + d4;
            float4 kvec = *(const float4*)&kv[gr];
            Ks[key * KSD + d4 + 0] = f2tf32(kvec.x);
            Ks[key * KSD + d4 + 1] = f2tf32(kvec.y);
            Ks[key * KSD + d4 + 2] = f2tf32(kvec.z);
            Ks[key * KSD + d4 + 3] = f2tf32(kvec.w);
            float4 vvec = *(const float4*)&kv[gr + D_MODEL];
            Vs[key * VSD + d4 + 0] = f2tf32(vvec.x);
            Vs[key * VSD + d4 + 1] = f2tf32(vvec.y);
            Vs[key * VSD + d4 + 2] = f2tf32(vvec.z);
            Vs[key * VSD + d4 + 3] = f2tf32(vvec.w);
        }
        __syncthreads();

        // ---- S = Q K^T : warp rows 16w..16w+15, 64 keys ----
        float s[8][4];
        #pragma unroll
        for (int nt = 0; nt < 8; nt++)
            #pragma unroll
            for (int i = 0; i < 4; i++) s[nt][i] = 0.f;

        #pragma unroll
        for (int kb = 0; kb < 8; kb++) {
            const uint32_t* krow = &Ks[g * KSD + kb * 8 + q];
            #pragma unroll
            for (int nt = 0; nt < 8; nt++) {
                uint32_t bf[2];
                bf[0] = krow[(nt * 8) * KSD];
                bf[1] = krow[(nt * 8) * KSD + 4];
                mma_tf32(s[nt], qf[kb], bf);
            }
        }

        // ---- online softmax on fragment layout ----
        float mx0 = -1e30f, mx1 = -1e30f;
        #pragma unroll
        for (int nt = 0; nt < 8; nt++) {
            mx0 = fmaxf(mx0, fmaxf(s[nt][0], s[nt][1]));
            mx1 = fmaxf(mx1, fmaxf(s[nt][2], s[nt][3]));
        }
        mx0 = fmaxf(mx0, __shfl_xor_sync(0xffffffffu, mx0, 1));
        mx0 = fmaxf(mx0, __shfl_xor_sync(0xffffffffu, mx0, 2));
        mx1 = fmaxf(mx1, __shfl_xor_sync(0xffffffffu, mx1, 1));
        mx1 = fmaxf(mx1, __shfl_xor_sync(0xffffffffu, mx1, 2));

        float mn0 = fmaxf(mrow0, mx0), mn1 = fmaxf(mrow1, mx1);
        float cor0 = __expf(mrow0 - mn0), cor1 = __expf(mrow1 - mn1);
        float sum0 = 0.f, sum1 = 0.f;

        #pragma unroll
        for (int nt = 0; nt < 8; nt++) {
            float p00 = __expf(s[nt][0] - mn0);
            float p01 = __expf(s[nt][1] - mn0);
            float p10 = __expf(s[nt][2] - mn1);
            float p11 = __expf(s[nt][3] - mn1);
            sum0 += p00 + p01;
            sum1 += p10 + p11;
            int col = nt * 8 + 2 * q;
            Ps[r0       * QS + col]     = f2tf32(p00);
            Ps[r0       * QS + col + 1] = f2tf32(p01);
            Ps[(r0 + 8) * QS + col]     = f2tf32(p10);
            Ps[(r0 + 8) * QS + col + 1] = f2tf32(p11);
        }
        sum0 += __shfl_xor_sync(0xffffffffu, sum0, 1);
        sum0 += __shfl_xor_sync(0xffffffffu, sum0, 2);
        sum1 += __shfl_xor_sync(0xffffffffu, sum1, 1);
        sum1 += __shfl_xor_sync(0xffffffffu, sum1, 2);

        lrow0 = lrow0 * cor0 + sum0;
        lrow1 = lrow1 * cor1 + sum1;
        mrow0 = mn0;
        mrow1 = mn1;
        #pragma unroll
        for (int nt = 0; nt < 8; nt++) {
            o[nt][0] *= cor0; o[nt][1] *= cor0;
            o[nt][2] *= cor1; o[nt][3] *= cor1;
        }
        __syncwarp();

        // ---- O += P V : k = 64 keys, n = 64 dims ----
        #pragma unroll
        for (int kb = 0; kb < 8; kb++) {
            uint32_t pa[4];
            pa[0] = Ps[r0       * QS + kb * 8 + q];
            pa[1] = Ps[(r0 + 8) * QS + kb * 8 + q];
            pa[2] = Ps[r0       * QS + kb * 8 + q + 4];
            pa[3] = Ps[(r0 + 8) * QS + kb * 8 + q + 4];
            #pragma unroll
            for (int nt = 0; nt < 8; nt++) {
                uint32_t vf[2];
                vf[0] = Vs[(kb * 8 + q)     * VSD + nt * 8 + g];
                vf[1] = Vs[(kb * 8 + q + 4) * VSD + nt * 8 + g];
                mma_tf32(o[nt], pa, vf);
            }
        }
        __syncwarp();
    }

    // ---- epilogue ----
    float inv0 = 1.0f / lrow0, inv1 = 1.0f / lrow1;
    #pragma unroll
    for (int nt = 0; nt < 8; nt++) {
        int col = hbase + nt * 8 + 2 * q;
        *(float2*)&ao[(size_t)(qbase + r0) * D_MODEL + col] =
            make_float2(o[nt][0] * inv0, o[nt][1] * inv0);
        *(float2*)&ao[(size_t)(qbase + r0 + 8) * D_MODEL + col] =
            make_float2(o[nt][2] * inv1, o[nt][3] * inv1);
    }
}

// ---------------------------------------------------------------------------
extern "C" void kernel_launch(void* const* d_in, const int* in_sizes, int n_in,
                              void* d_out, int out_size)
{
    (void)in_sizes; (void)n_in; (void)out_size;
    const float* q     = (const float*)d_in[0];
    const float* gamma = (const float*)d_in[1];
    const float* beta  = (const float*)d_in[2];
    const float* Wq    = (const float*)d_in[3];
    const float* Wkv   = (const float*)d_in[4];
    const float* Wo    = (const float*)d_in[5];
    float* out = (float*)d_out;

    float *x, *qp, *kvb, *ao;
    cudaGetSymbolAddress((void**)&x,   g_x);
    cudaGetSymbolAddress((void**)&qp,  g_qp);
    cudaGetSymbolAddress((void**)&kvb, g_kv);
    cudaGetSymbolAddress((void**)&ao,  g_ao);

    cudaFuncSetAttribute(attn_tf32_kernel,
                         cudaFuncAttributeMaxDynamicSharedMemorySize, ATTN_SMEM_BYTES);

    ln_kernel<<<N_TOK, 256>>>(q, gamma, beta, x);

    gemm_tf32x3_kernel<<<dim3(D_MODEL/128, N_TOK/128), 256>>>(x, Wq,  qp,  N_TOK, D_MODEL, D_MODEL);
    gemm_tf32x3_kernel<<<dim3(KV_DIM/128,  N_TOK/128), 256>>>(x, Wkv, kvb, N_TOK, KV_DIM,  D_MODEL);

    attn_tf32_kernel<<<dim3(N_TOK/128, N_HEADS), 256, ATTN_SMEM_BYTES>>>(qp, kvb, ao);

    gemm_tf32x3_kernel<<<dim3(D_MODEL/128, N_TOK/128), 256>>>(ao, Wo, out, N_TOK, D_MODEL, D_MODEL);
}

// round 6
// speedup vs baseline: 2.0554x; 1.0818x over previous
#include <cuda_runtime.h>
#include <stdint.h>
#include <math.h>

#define N_TOK   4096
#define D_MODEL 1024
#define N_HEADS 16
#define HD      64
#define KV_DIM  2048

// ---------------- scratch (device globals; no allocation allowed) ----------
__device__ float g_x [N_TOK * D_MODEL];   // layernorm output
__device__ float g_qp[N_TOK * D_MODEL];   // q projection  [n, h*64+d]
__device__ float g_kv[N_TOK * KV_DIM];    // kv projection [n, 2048] (tf32-rounded)
__device__ float g_ao[N_TOK * D_MODEL];   // attention output [n, h*64+d]

// ---------------------------------------------------------------------------
// helpers
// ---------------------------------------------------------------------------
__device__ __forceinline__ uint32_t f2tf32(float f) {
    uint32_t r;
    asm("cvt.rna.tf32.f32 %0, %1;" : "=r"(r) : "f"(f));
    return r;
}

__device__ __forceinline__ void mma_tf32(float c[4], const uint32_t a[4], const uint32_t b[2]) {
    asm volatile(
        "mma.sync.aligned.m16n8k8.row.col.f32.tf32.tf32.f32 "
        "{%0,%1,%2,%3}, {%4,%5,%6,%7}, {%8,%9}, {%0,%1,%2,%3};"
        : "+f"(c[0]), "+f"(c[1]), "+f"(c[2]), "+f"(c[3])
        : "r"(a[0]), "r"(a[1]), "r"(a[2]), "r"(a[3]), "r"(b[0]), "r"(b[1]));
}

__device__ __forceinline__ void cp_async16(uint32_t saddr, const void* gaddr) {
    asm volatile("cp.async.cg.shared.global [%0], [%1], 16;\n" :: "r"(saddr), "l"(gaddr));
}
#define CP_COMMIT() asm volatile("cp.async.commit_group;\n" ::: "memory")
#define CP_WAIT(n)  asm volatile("cp.async.wait_group %0;\n" :: "n"(n) : "memory")

// ---------------------------------------------------------------------------
// LayerNorm
// ---------------------------------------------------------------------------
__device__ __forceinline__ float block_allreduce(float v) {
    __shared__ float red[8];
    __shared__ float bc;
    #pragma unroll
    for (int m = 16; m >= 1; m >>= 1) v += __shfl_xor_sync(0xffffffffu, v, m);
    if ((threadIdx.x & 31) == 0) red[threadIdx.x >> 5] = v;
    __syncthreads();
    if (threadIdx.x == 0) {
        float t = 0.f;
        #pragma unroll
        for (int i = 0; i < 8; i++) t += red[i];
        bc = t;
    }
    __syncthreads();
    float r = bc;
    __syncthreads();
    return r;
}

__global__ __launch_bounds__(256) void ln_kernel(
    const float* __restrict__ q, const float* __restrict__ gamma,
    const float* __restrict__ beta, float* __restrict__ x)
{
    int row = blockIdx.x;
    int tid = threadIdx.x;
    const float4 v = ((const float4*)(q + (size_t)row * D_MODEL))[tid];

    float s = v.x + v.y + v.z + v.w;
    float mu = block_allreduce(s) * (1.0f / D_MODEL);

    float dx = v.x - mu, dy = v.y - mu, dz = v.z - mu, dw = v.w - mu;
    float var = block_allreduce(dx*dx + dy*dy + dz*dz + dw*dw) * (1.0f / D_MODEL);
    float rstd = rsqrtf(var + 1e-5f);

    const float4 g = ((const float4*)gamma)[tid];
    const float4 b = ((const float4*)beta)[tid];
    float4 o;
    o.x = dx * rstd * g.x + b.x;
    o.y = dy * rstd * g.y + b.y;
    o.z = dz * rstd * g.z + b.z;
    o.w = dw * rstd * g.w + b.w;
    ((float4*)(x + (size_t)row * D_MODEL))[tid] = o;
}

// ---------------------------------------------------------------------------
// GEMM (3xTF32, register-pipelined): C[M,N] = A[M,K] @ B[N,K]^T
// round_out != 0 -> store rna-tf32-rounded fp32 (for attention K/V consumer).
// ---------------------------------------------------------------------------
#define GS 20

__global__ __launch_bounds__(256) void gemm_tf32x3_kernel(
    const float* __restrict__ A, const float* __restrict__ B,
    float* __restrict__ C, int M, int N, int K, int round_out)
{
    __shared__ uint32_t Ah[128 * GS], Al[128 * GS];
    __shared__ uint32_t Bh[128 * GS], Bl[128 * GS];

    const int tid  = threadIdx.x;
    const int lane = tid & 31;
    const int warp = tid >> 5;
    const int wm   = (warp >> 1) * 32;
    const int wn   = (warp & 1) * 64;
    const int g    = lane >> 2;
    const int q    = lane & 3;
    const int brow = blockIdx.y * 128;
    const int bcol = blockIdx.x * 128;

    const int row0 = tid >> 2;            // 0..63
    const int row1 = row0 + 64;
    const int c4   = (tid & 3) * 4;

    float acc[2][8][4];
    #pragma unroll
    for (int mt = 0; mt < 2; mt++)
        #pragma unroll
        for (int nt = 0; nt < 8; nt++)
            #pragma unroll
            for (int i = 0; i < 4; i++) acc[mt][nt][i] = 0.f;

    // prologue: prefetch k-tile 0
    float4 va0 = *(const float4*)&A[(size_t)(brow + row0) * K + c4];
    float4 va1 = *(const float4*)&A[(size_t)(brow + row1) * K + c4];
    float4 vb0 = *(const float4*)&B[(size_t)(bcol + row0) * K + c4];
    float4 vb1 = *(const float4*)&B[(size_t)(bcol + row1) * K + c4];

    for (int k0 = 0; k0 < K; k0 += 16) {
        __syncthreads();
        {
            float av0[4] = {va0.x, va0.y, va0.z, va0.w};
            float av1[4] = {va1.x, va1.y, va1.z, va1.w};
            float bv0[4] = {vb0.x, vb0.y, vb0.z, vb0.w};
            float bv1[4] = {vb1.x, vb1.y, vb1.z, vb1.w};
            #pragma unroll
            for (int j = 0; j < 4; j++) {
                uint32_t h;
                h = f2tf32(av0[j]); Ah[row0 * GS + c4 + j] = h;
                Al[row0 * GS + c4 + j] = f2tf32(av0[j] - __uint_as_float(h));
                h = f2tf32(av1[j]); Ah[row1 * GS + c4 + j] = h;
                Al[row1 * GS + c4 + j] = f2tf32(av1[j] - __uint_as_float(h));
                h = f2tf32(bv0[j]); Bh[row0 * GS + c4 + j] = h;
                Bl[row0 * GS + c4 + j] = f2tf32(bv0[j] - __uint_as_float(h));
                h = f2tf32(bv1[j]); Bh[row1 * GS + c4 + j] = h;
                Bl[row1 * GS + c4 + j] = f2tf32(bv1[j] - __uint_as_float(h));
            }
        }
        __syncthreads();

        if (k0 + 16 < K) {   // prefetch next tile (overlaps with MMAs below)
            va0 = *(const float4*)&A[(size_t)(brow + row0) * K + k0 + 16 + c4];
            va1 = *(const float4*)&A[(size_t)(brow + row1) * K + k0 + 16 + c4];
            vb0 = *(const float4*)&B[(size_t)(bcol + row0) * K + k0 + 16 + c4];
            vb1 = *(const float4*)&B[(size_t)(bcol + row1) * K + k0 + 16 + c4];
        }

        #pragma unroll
        for (int kb = 0; kb < 16; kb += 8) {
            uint32_t ah[2][4], al[2][4], bh[8][2], bl[8][2];
            #pragma unroll
            for (int mt = 0; mt < 2; mt++) {
                int r0 = wm + mt * 16 + g;
                ah[mt][0] = Ah[r0       * GS + kb + q];
                ah[mt][1] = Ah[(r0 + 8) * GS + kb + q];
                ah[mt][2] = Ah[r0       * GS + kb + q + 4];
                ah[mt][3] = Ah[(r0 + 8) * GS + kb + q + 4];
                al[mt][0] = Al[r0       * GS + kb + q];
                al[mt][1] = Al[(r0 + 8) * GS + kb + q];
                al[mt][2] = Al[r0       * GS + kb + q + 4];
                al[mt][3] = Al[(r0 + 8) * GS + kb + q + 4];
            }
            #pragma unroll
            for (int nt = 0; nt < 8; nt++) {
                int n0 = wn + nt * 8 + g;
                bh[nt][0] = Bh[n0 * GS + kb + q];
                bh[nt][1] = Bh[n0 * GS + kb + q + 4];
                bl[nt][0] = Bl[n0 * GS + kb + q];
                bl[nt][1] = Bl[n0 * GS + kb + q + 4];
            }
            #pragma unroll
            for (int mt = 0; mt < 2; mt++)
                #pragma unroll
                for (int nt = 0; nt < 8; nt++)
                    mma_tf32(acc[mt][nt], ah[mt], bh[nt]);
            #pragma unroll
            for (int mt = 0; mt < 2; mt++)
                #pragma unroll
                for (int nt = 0; nt < 8; nt++)
                    mma_tf32(acc[mt][nt], al[mt], bh[nt]);
            #pragma unroll
            for (int mt = 0; mt < 2; mt++)
                #pragma unroll
                for (int nt = 0; nt < 8; nt++)
                    mma_tf32(acc[mt][nt], ah[mt], bl[nt]);
        }
    }

    if (round_out) {
        #pragma unroll
        for (int mt = 0; mt < 2; mt++)
            #pragma unroll
            for (int nt = 0; nt < 8; nt++)
                #pragma unroll
                for (int i = 0; i < 4; i++)
                    acc[mt][nt][i] = __uint_as_float(f2tf32(acc[mt][nt][i]));
    }

    #pragma unroll
    for (int mt = 0; mt < 2; mt++) {
        int r0 = brow + wm + mt * 16 + g;
        #pragma unroll
        for (int nt = 0; nt < 8; nt++) {
            int cc = bcol + wn + nt * 8 + 2 * q;
            *(float2*)&C[(size_t)r0 * N + cc]       = make_float2(acc[mt][nt][0], acc[mt][nt][1]);
            *(float2*)&C[(size_t)(r0 + 8) * N + cc] = make_float2(acc[mt][nt][2], acc[mt][nt][3]);
        }
    }
}

// ---------------------------------------------------------------------------
// Flash attention, tf32 mma, cp.async double-buffered K/V (values pre-rounded
// to tf32 by the Wkv GEMM epilogue), P rna-rounded in registers, P fragments
// via warp shuffles (no smem round-trip).
// Block = 256 thr (8 warps); warp w owns query rows 16w..16w+15; KV tile = 64.
// ---------------------------------------------------------------------------
#define QS  68
#define KSD 68
#define VSD 72
#define KVBUF (64 * KSD + 64 * VSD)            // words per stage
#define ATTN_SMEM_BYTES (2 * KVBUF * 4)        // 71680 (Q stage fits inside)

__global__ __launch_bounds__(256) void attn_tf32_kernel(
    const float* __restrict__ qp, const float* __restrict__ kv,
    float* __restrict__ ao)
{
    extern __shared__ uint32_t sm[];

    const int tid   = threadIdx.x;
    const int lane  = tid & 31;
    const int warp  = tid >> 5;
    const int g     = lane >> 2;
    const int q     = lane & 3;
    const int qbase = blockIdx.x * 128;
    const int hbase = blockIdx.y * HD;
    const int r0    = warp * 16 + g;

    // ---- stage Q (scaled, rna tf32) into sm[0..128*QS) and preload frags ----
    #pragma unroll
    for (int r = 0; r < 8; r++) {
        int e   = tid + 256 * r;
        int row = e >> 4;
        int d4  = (e & 15) * 4;
        float4 v = *(const float4*)&qp[(size_t)(qbase + row) * D_MODEL + hbase + d4];
        sm[row * QS + d4 + 0] = f2tf32(v.x * 0.125f);
        sm[row * QS + d4 + 1] = f2tf32(v.y * 0.125f);
        sm[row * QS + d4 + 2] = f2tf32(v.z * 0.125f);
        sm[row * QS + d4 + 3] = f2tf32(v.w * 0.125f);
    }
    __syncthreads();

    uint32_t qf[8][4];
    #pragma unroll
    for (int kb = 0; kb < 8; kb++) {
        qf[kb][0] = sm[r0       * QS + kb * 8 + q];
        qf[kb][1] = sm[(r0 + 8) * QS + kb * 8 + q];
        qf[kb][2] = sm[r0       * QS + kb * 8 + q + 4];
        qf[kb][3] = sm[(r0 + 8) * QS + kb * 8 + q + 4];
    }
    __syncthreads();   // Q reads done; smem now reused as K/V double buffers

    const uint32_t smem_base = (uint32_t)__cvta_generic_to_shared(sm);

    // ---- prefetch tile 0 into buffer 0 ----
    {
        #pragma unroll
        for (int r = 0; r < 4; r++) {
            int e   = tid + 256 * r;
            int key = e >> 4;
            int c16 = e & 15;
            size_t gr = (size_t)key * KV_DIM + hbase + c16 * 4;
            cp_async16(smem_base + (uint32_t)(key * KSD + c16 * 4) * 4, kv + gr);
            cp_async16(smem_base + (uint32_t)(64 * KSD + key * VSD + c16 * 4) * 4, kv + gr + D_MODEL);
        }
        CP_COMMIT();
    }

    float o[8][4];
    #pragma unroll
    for (int nt = 0; nt < 8; nt++)
        #pragma unroll
        for (int i = 0; i < 4; i++) o[nt][i] = 0.f;
    float mrow0 = -1e30f, mrow1 = -1e30f, lrow0 = 0.f, lrow1 = 0.f;

    const int NT = N_TOK / 64;
    for (int t = 0; t < NT; t++) {
        __syncthreads();   // everyone done reading buf[(t+1)&1] from iteration t-1

        if (t + 1 < NT) {
            uint32_t boff = (uint32_t)(((t + 1) & 1) * KVBUF);
            #pragma unroll
            for (int r = 0; r < 4; r++) {
                int e   = tid + 256 * r;
                int key = e >> 4;
                int c16 = e & 15;
                size_t gr = (size_t)((t + 1) * 64 + key) * KV_DIM + hbase + c16 * 4;
                cp_async16(smem_base + (boff + key * KSD + c16 * 4) * 4, kv + gr);
                cp_async16(smem_base + (boff + 64 * KSD + key * VSD + c16 * 4) * 4, kv + gr + D_MODEL);
            }
            CP_COMMIT();
            CP_WAIT(1);
        } else {
            CP_WAIT(0);
        }
        __syncthreads();   // buf[t&1] visible to all

        const uint32_t* Ks = sm + (t & 1) * KVBUF;
        const uint32_t* Vs = Ks + 64 * KSD;

        // ---- S = Q K^T ----
        float s[8][4];
        #pragma unroll
        for (int nt = 0; nt < 8; nt++)
            #pragma unroll
            for (int i = 0; i < 4; i++) s[nt][i] = 0.f;

        #pragma unroll
        for (int kb = 0; kb < 8; kb++) {
            const uint32_t* krow = &Ks[g * KSD + kb * 8 + q];
            #pragma unroll
            for (int nt = 0; nt < 8; nt++) {
                uint32_t bf[2];
                bf[0] = krow[(nt * 8) * KSD];
                bf[1] = krow[(nt * 8) * KSD + 4];
                mma_tf32(s[nt], qf[kb], bf);
            }
        }

        // ---- online softmax (fragment layout) ----
        float mx0 = -1e30f, mx1 = -1e30f;
        #pragma unroll
        for (int nt = 0; nt < 8; nt++) {
            mx0 = fmaxf(mx0, fmaxf(s[nt][0], s[nt][1]));
            mx1 = fmaxf(mx1, fmaxf(s[nt][2], s[nt][3]));
        }
        mx0 = fmaxf(mx0, __shfl_xor_sync(0xffffffffu, mx0, 1));
        mx0 = fmaxf(mx0, __shfl_xor_sync(0xffffffffu, mx0, 2));
        mx1 = fmaxf(mx1, __shfl_xor_sync(0xffffffffu, mx1, 1));
        mx1 = fmaxf(mx1, __shfl_xor_sync(0xffffffffu, mx1, 2));

        float mn0 = fmaxf(mrow0, mx0), mn1 = fmaxf(mrow1, mx1);
        float cor0 = __expf(mrow0 - mn0), cor1 = __expf(mrow1 - mn1);
        float sum0 = 0.f, sum1 = 0.f;

        #pragma unroll
        for (int nt = 0; nt < 8; nt++) {
            s[nt][0] = __expf(s[nt][0] - mn0);
            s[nt][1] = __expf(s[nt][1] - mn0);
            s[nt][2] = __expf(s[nt][2] - mn1);
            s[nt][3] = __expf(s[nt][3] - mn1);
            sum0 += s[nt][0] + s[nt][1];
            sum1 += s[nt][2] + s[nt][3];
        }
        sum0 += __shfl_xor_sync(0xffffffffu, sum0, 1);
        sum0 += __shfl_xor_sync(0xffffffffu, sum0, 2);
        sum1 += __shfl_xor_sync(0xffffffffu, sum1, 1);
        sum1 += __shfl_xor_sync(0xffffffffu, sum1, 2);

        lrow0 = lrow0 * cor0 + sum0;
        lrow1 = lrow1 * cor1 + sum1;
        mrow0 = mn0;
        mrow1 = mn1;
        #pragma unroll
        for (int nt = 0; nt < 8; nt++) {
            o[nt][0] *= cor0; o[nt][1] *= cor0;
            o[nt][2] *= cor1; o[nt][3] *= cor1;
        }

        // ---- O += P V : P fragments via shuffles, rna-rounded to tf32 ----
        const int l0 = g * 4 + (q >> 1);   // src lane for col group c=q
        const int l1 = l0 + 2;             // src lane for col group c=q+4
        const bool odd = (q & 1);
        #pragma unroll
        for (int kb = 0; kb < 8; kb++) {
            float t0  = __shfl_sync(0xffffffffu, s[kb][0], l0);
            float t1  = __shfl_sync(0xffffffffu, s[kb][1], l0);
            float t2  = __shfl_sync(0xffffffffu, s[kb][2], l0);
            float t3  = __shfl_sync(0xffffffffu, s[kb][3], l0);
            float u0  = __shfl_sync(0xffffffffu, s[kb][0], l1);
            float u1  = __shfl_sync(0xffffffffu, s[kb][1], l1);
            float u2  = __shfl_sync(0xffffffffu, s[kb][2], l1);
            float u3  = __shfl_sync(0xffffffffu, s[kb][3], l1);
            uint32_t pa[4];
            pa[0] = f2tf32(odd ? t1 : t0);   // (row g,   k=q)
            pa[1] = f2tf32(odd ? t3 : t2);   // (row g+8, k=q)
            pa[2] = f2tf32(odd ? u1 : u0);   // (row g,   k=q+4)
            pa[3] = f2tf32(odd ? u3 : u2);   // (row g+8, k=q+4)

            const uint32_t* vrow = &Vs[(kb * 8 + q) * VSD + g];
            #pragma unroll
            for (int nt = 0; nt < 8; nt++) {
                uint32_t vf[2];
                vf[0] = vrow[nt * 8];
                vf[1] = vrow[4 * VSD + nt * 8];
                mma_tf32(o[nt], pa, vf);
            }
        }
    }

    // ---- epilogue ----
    float inv0 = 1.0f / lrow0, inv1 = 1.0f / lrow1;
    #pragma unroll
    for (int nt = 0; nt < 8; nt++) {
        int col = hbase + nt * 8 + 2 * q;
        *(float2*)&ao[(size_t)(qbase + r0) * D_MODEL + col] =
            make_float2(o[nt][0] * inv0, o[nt][1] * inv0);
        *(float2*)&ao[(size_t)(qbase + r0 + 8) * D_MODEL + col] =
            make_float2(o[nt][2] * inv1, o[nt][3] * inv1);
    }
}

// ---------------------------------------------------------------------------
extern "C" void kernel_launch(void* const* d_in, const int* in_sizes, int n_in,
                              void* d_out, int out_size)
{
    (void)in_sizes; (void)n_in; (void)out_size;
    const float* q     = (const float*)d_in[0];
    const float* gamma = (const float*)d_in[1];
    const float* beta  = (const float*)d_in[2];
    const float* Wq    = (const float*)d_in[3];
    const float* Wkv   = (const float*)d_in[4];
    const float* Wo    = (const float*)d_in[5];
    float* out = (float*)d_out;

    float *x, *qp, *kvb, *ao;
    cudaGetSymbolAddress((void**)&x,   g_x);
    cudaGetSymbolAddress((void**)&qp,  g_qp);
    cudaGetSymbolAddress((void**)&kvb, g_kv);
    cudaGetSymbolAddress((void**)&ao,  g_ao);

    cudaFuncSetAttribute(attn_tf32_kernel,
                         cudaFuncAttributeMaxDynamicSharedMemorySize, ATTN_SMEM_BYTES);

    ln_kernel<<<N_TOK, 256>>>(q, gamma, beta, x);

    gemm_tf32x3_kernel<<<dim3(D_MODEL/128, N_TOK/128), 256>>>(x, Wq,  qp,  N_TOK, D_MODEL, D_MODEL, 0);
    gemm_tf32x3_kernel<<<dim3(KV_DIM/128,  N_TOK/128), 256>>>(x, Wkv, kvb, N_TOK, KV_DIM,  D_MODEL, 1);

    attn_tf32_kernel<<<dim3(N_TOK/128, N_HEADS), 256, ATTN_SMEM_BYTES>>>(qp, kvb, ao);

    gemm_tf32x3_kernel<<<dim3(D_MODEL/128, N_TOK/128), 256>>>(ao, Wo, out, N_TOK, D_MODEL, D_MODEL, 0);
}

// round 7
// speedup vs baseline: 3.1507x; 1.5329x over previous
#include <cuda_runtime.h>
#include <cuda_bf16.h>
#include <stdint.h>
#include <math.h>

#define N_TOK   4096
#define D_MODEL 1024
#define N_HEADS 16
#define HD      64
#define KV_DIM  2048

// ---------------- scratch (device globals; no allocation allowed) ----------
__device__ float g_x [N_TOK * D_MODEL];   // layernorm output
__device__ float g_qp[N_TOK * D_MODEL];   // q projection  [n, h*64+d]
__device__ float g_kv[N_TOK * KV_DIM];    // kv projection [n, 2048] (tf32-rounded)
__device__ float g_ao[N_TOK * D_MODEL];   // attention output [n, h*64+d]

// ---------------------------------------------------------------------------
// helpers
// ---------------------------------------------------------------------------
__device__ __forceinline__ uint32_t f2tf32(float f) {
    uint32_t r;
    asm("cvt.rna.tf32.f32 %0, %1;" : "=r"(r) : "f"(f));
    return r;
}

__device__ __forceinline__ void mma_tf32(float c[4], const uint32_t a[4], const uint32_t b[2]) {
    asm volatile(
        "mma.sync.aligned.m16n8k8.row.col.f32.tf32.tf32.f32 "
        "{%0,%1,%2,%3}, {%4,%5,%6,%7}, {%8,%9}, {%0,%1,%2,%3};"
        : "+f"(c[0]), "+f"(c[1]), "+f"(c[2]), "+f"(c[3])
        : "r"(a[0]), "r"(a[1]), "r"(a[2]), "r"(a[3]), "r"(b[0]), "r"(b[1]));
}

__device__ __forceinline__ void mma_bf16(float c[4], const uint32_t a[4], const uint32_t b[2]) {
    asm volatile(
        "mma.sync.aligned.m16n8k16.row.col.f32.bf16.bf16.f32 "
        "{%0,%1,%2,%3}, {%4,%5,%6,%7}, {%8,%9}, {%0,%1,%2,%3};"
        : "+f"(c[0]), "+f"(c[1]), "+f"(c[2]), "+f"(c[3])
        : "r"(a[0]), "r"(a[1]), "r"(a[2]), "r"(a[3]), "r"(b[0]), "r"(b[1]));
}

__device__ __forceinline__ uint32_t pack_bf16(__nv_bfloat16 lo, __nv_bfloat16 hi) {
    __nv_bfloat162 t;
    t.x = lo; t.y = hi;
    return *reinterpret_cast<uint32_t*>(&t);
}

__device__ __forceinline__ void cp_async16(uint32_t saddr, const void* gaddr) {
    asm volatile("cp.async.cg.shared.global [%0], [%1], 16;\n" :: "r"(saddr), "l"(gaddr));
}
#define CP_COMMIT() asm volatile("cp.async.commit_group;\n" ::: "memory")
#define CP_WAIT(n)  asm volatile("cp.async.wait_group %0;\n" :: "n"(n) : "memory")

// ---------------------------------------------------------------------------
// LayerNorm
// ---------------------------------------------------------------------------
__device__ __forceinline__ float block_allreduce(float v) {
    __shared__ float red[8];
    __shared__ float bc;
    #pragma unroll
    for (int m = 16; m >= 1; m >>= 1) v += __shfl_xor_sync(0xffffffffu, v, m);
    if ((threadIdx.x & 31) == 0) red[threadIdx.x >> 5] = v;
    __syncthreads();
    if (threadIdx.x == 0) {
        float t = 0.f;
        #pragma unroll
        for (int i = 0; i < 8; i++) t += red[i];
        bc = t;
    }
    __syncthreads();
    float r = bc;
    __syncthreads();
    return r;
}

__global__ __launch_bounds__(256) void ln_kernel(
    const float* __restrict__ q, const float* __restrict__ gamma,
    const float* __restrict__ beta, float* __restrict__ x)
{
    int row = blockIdx.x;
    int tid = threadIdx.x;
    const float4 v = ((const float4*)(q + (size_t)row * D_MODEL))[tid];

    float s = v.x + v.y + v.z + v.w;
    float mu = block_allreduce(s) * (1.0f / D_MODEL);

    float dx = v.x - mu, dy = v.y - mu, dz = v.z - mu, dw = v.w - mu;
    float var = block_allreduce(dx*dx + dy*dy + dz*dz + dw*dw) * (1.0f / D_MODEL);
    float rstd = rsqrtf(var + 1e-5f);

    const float4 g = ((const float4*)gamma)[tid];
    const float4 b = ((const float4*)beta)[tid];
    float4 o;
    o.x = dx * rstd * g.x + b.x;
    o.y = dy * rstd * g.y + b.y;
    o.z = dz * rstd * g.z + b.z;
    o.w = dw * rstd * g.w + b.w;
    ((float4*)(x + (size_t)row * D_MODEL))[tid] = o;
}

// ---------------------------------------------------------------------------
// GEMM (3xBF16, register-pipelined): C[M,N] = A[M,K] @ B[N,K]^T
// Split x = xh(bf16) + xl(bf16 residual); C = ah*bh + al*bh + ah*bl.
// 128x128 block tile, 16 K-tile, m16n8k16 mma. smem rows = 8 packed words,
// stride 12 (== 12 mod 32 gives all-distinct frag-load banks).
// round_out != 0 -> store rna-tf32-rounded fp32 (for attention K/V consumer).
// ---------------------------------------------------------------------------
#define WS 12

__global__ __launch_bounds__(256) void gemm_bf16x3_kernel(
    const float* __restrict__ A, const float* __restrict__ B,
    float* __restrict__ C, int M, int N, int K, int round_out)
{
    __shared__ uint32_t Ah[128 * WS], Al[128 * WS];
    __shared__ uint32_t Bh[128 * WS], Bl[128 * WS];

    const int tid  = threadIdx.x;
    const int lane = tid & 31;
    const int warp = tid >> 5;
    const int wm   = (warp >> 1) * 32;
    const int wn   = (warp & 1) * 64;
    const int g    = lane >> 2;
    const int q    = lane & 3;
    const int brow = blockIdx.y * 128;
    const int bcol = blockIdx.x * 128;

    const int row0 = tid >> 2;            // 0..63
    const int row1 = row0 + 64;
    const int c4   = (tid & 3) * 4;       // first float (of 4) in the 16-k row
    const int w0   = (tid & 3) * 2;       // first packed word

    float acc[2][8][4];
    #pragma unroll
    for (int mt = 0; mt < 2; mt++)
        #pragma unroll
        for (int nt = 0; nt < 8; nt++)
            #pragma unroll
            for (int i = 0; i < 4; i++) acc[mt][nt][i] = 0.f;

    // prologue: prefetch k-tile 0
    float4 va0 = *(const float4*)&A[(size_t)(brow + row0) * K + c4];
    float4 va1 = *(const float4*)&A[(size_t)(brow + row1) * K + c4];
    float4 vb0 = *(const float4*)&B[(size_t)(bcol + row0) * K + c4];
    float4 vb1 = *(const float4*)&B[(size_t)(bcol + row1) * K + c4];

    for (int k0 = 0; k0 < K; k0 += 16) {
        __syncthreads();
        {
            // split + pack one float4 -> 2 high words + 2 low words
            #define SPLIT_STORE(SH, SL, ROW, V)                                         \
            {                                                                            \
                __nv_bfloat16 h0 = __float2bfloat16_rn(V.x);                             \
                __nv_bfloat16 h1 = __float2bfloat16_rn(V.y);                             \
                __nv_bfloat16 h2 = __float2bfloat16_rn(V.z);                             \
                __nv_bfloat16 h3 = __float2bfloat16_rn(V.w);                             \
                __nv_bfloat16 l0 = __float2bfloat16_rn(V.x - __bfloat162float(h0));      \
                __nv_bfloat16 l1 = __float2bfloat16_rn(V.y - __bfloat162float(h1));      \
                __nv_bfloat16 l2 = __float2bfloat16_rn(V.z - __bfloat162float(h2));      \
                __nv_bfloat16 l3 = __float2bfloat16_rn(V.w - __bfloat162float(h3));      \
                *(uint2*)&SH[(ROW) * WS + w0] =                                          \
                    make_uint2(pack_bf16(h0, h1), pack_bf16(h2, h3));                    \
                *(uint2*)&SL[(ROW) * WS + w0] =                                          \
                    make_uint2(pack_bf16(l0, l1), pack_bf16(l2, l3));                    \
            }
            SPLIT_STORE(Ah, Al, row0, va0);
            SPLIT_STORE(Ah, Al, row1, va1);
            SPLIT_STORE(Bh, Bl, row0, vb0);
            SPLIT_STORE(Bh, Bl, row1, vb1);
            #undef SPLIT_STORE
        }
        __syncthreads();

        if (k0 + 16 < K) {   // prefetch next tile (overlaps with MMAs below)
            va0 = *(const float4*)&A[(size_t)(brow + row0) * K + k0 + 16 + c4];
            va1 = *(const float4*)&A[(size_t)(brow + row1) * K + k0 + 16 + c4];
            vb0 = *(const float4*)&B[(size_t)(bcol + row0) * K + k0 + 16 + c4];
            vb1 = *(const float4*)&B[(size_t)(bcol + row1) * K + k0 + 16 + c4];
        }

        uint32_t ah[2][4], al[2][4], bh[8][2], bl[8][2];
        #pragma unroll
        for (int mt = 0; mt < 2; mt++) {
            int r0 = wm + mt * 16 + g;
            ah[mt][0] = Ah[r0       * WS + q];
            ah[mt][1] = Ah[(r0 + 8) * WS + q];
            ah[mt][2] = Ah[r0       * WS + q + 4];
            ah[mt][3] = Ah[(r0 + 8) * WS + q + 4];
            al[mt][0] = Al[r0       * WS + q];
            al[mt][1] = Al[(r0 + 8) * WS + q];
            al[mt][2] = Al[r0       * WS + q + 4];
            al[mt][3] = Al[(r0 + 8) * WS + q + 4];
        }
        #pragma unroll
        for (int nt = 0; nt < 8; nt++) {
            int n0 = wn + nt * 8 + g;
            bh[nt][0] = Bh[n0 * WS + q];
            bh[nt][1] = Bh[n0 * WS + q + 4];
            bl[nt][0] = Bl[n0 * WS + q];
            bl[nt][1] = Bl[n0 * WS + q + 4];
        }
        #pragma unroll
        for (int mt = 0; mt < 2; mt++)
            #pragma unroll
            for (int nt = 0; nt < 8; nt++)
                mma_bf16(acc[mt][nt], ah[mt], bh[nt]);
        #pragma unroll
        for (int mt = 0; mt < 2; mt++)
            #pragma unroll
            for (int nt = 0; nt < 8; nt++)
                mma_bf16(acc[mt][nt], al[mt], bh[nt]);
        #pragma unroll
        for (int mt = 0; mt < 2; mt++)
            #pragma unroll
            for (int nt = 0; nt < 8; nt++)
                mma_bf16(acc[mt][nt], ah[mt], bl[nt]);
    }

    if (round_out) {
        #pragma unroll
        for (int mt = 0; mt < 2; mt++)
            #pragma unroll
            for (int nt = 0; nt < 8; nt++)
                #pragma unroll
                for (int i = 0; i < 4; i++)
                    acc[mt][nt][i] = __uint_as_float(f2tf32(acc[mt][nt][i]));
    }

    #pragma unroll
    for (int mt = 0; mt < 2; mt++) {
        int r0 = brow + wm + mt * 16 + g;
        #pragma unroll
        for (int nt = 0; nt < 8; nt++) {
            int cc = bcol + wn + nt * 8 + 2 * q;
            *(float2*)&C[(size_t)r0 * N + cc]       = make_float2(acc[mt][nt][0], acc[mt][nt][1]);
            *(float2*)&C[(size_t)(r0 + 8) * N + cc] = make_float2(acc[mt][nt][2], acc[mt][nt][3]);
        }
    }
}

// ---------------------------------------------------------------------------
// Flash attention, tf32 mma, cp.async double-buffered K/V (values pre-rounded
// to tf32 by the Wkv GEMM epilogue), P rna-rounded in registers, P fragments
// via warp shuffles (no smem round-trip).
// Block = 256 thr (8 warps); warp w owns query rows 16w..16w+15; KV tile = 64.
// ---------------------------------------------------------------------------
#define QS  68
#define KSD 68
#define VSD 72
#define KVBUF (64 * KSD + 64 * VSD)            // words per stage
#define ATTN_SMEM_BYTES (2 * KVBUF * 4)        // 71680 (Q stage fits inside)

__global__ __launch_bounds__(256) void attn_tf32_kernel(
    const float* __restrict__ qp, const float* __restrict__ kv,
    float* __restrict__ ao)
{
    extern __shared__ uint32_t sm[];

    const int tid   = threadIdx.x;
    const int lane  = tid & 31;
    const int warp  = tid >> 5;
    const int g     = lane >> 2;
    const int q     = lane & 3;
    const int qbase = blockIdx.x * 128;
    const int hbase = blockIdx.y * HD;
    const int r0    = warp * 16 + g;

    // ---- stage Q (scaled, rna tf32) into sm[0..128*QS) and preload frags ----
    #pragma unroll
    for (int r = 0; r < 8; r++) {
        int e   = tid + 256 * r;
        int row = e >> 4;
        int d4  = (e & 15) * 4;
        float4 v = *(const float4*)&qp[(size_t)(qbase + row) * D_MODEL + hbase + d4];
        sm[row * QS + d4 + 0] = f2tf32(v.x * 0.125f);
        sm[row * QS + d4 + 1] = f2tf32(v.y * 0.125f);
        sm[row * QS + d4 + 2] = f2tf32(v.z * 0.125f);
        sm[row * QS + d4 + 3] = f2tf32(v.w * 0.125f);
    }
    __syncthreads();

    uint32_t qf[8][4];
    #pragma unroll
    for (int kb = 0; kb < 8; kb++) {
        qf[kb][0] = sm[r0       * QS + kb * 8 + q];
        qf[kb][1] = sm[(r0 + 8) * QS + kb * 8 + q];
        qf[kb][2] = sm[r0       * QS + kb * 8 + q + 4];
        qf[kb][3] = sm[(r0 + 8) * QS + kb * 8 + q + 4];
    }
    __syncthreads();   // Q reads done; smem now reused as K/V double buffers

    const uint32_t smem_base = (uint32_t)__cvta_generic_to_shared(sm);

    // ---- prefetch tile 0 into buffer 0 ----
    {
        #pragma unroll
        for (int r = 0; r < 4; r++) {
            int e   = tid + 256 * r;
            int key = e >> 4;
            int c16 = e & 15;
            size_t gr = (size_t)key * KV_DIM + hbase + c16 * 4;
            cp_async16(smem_base + (uint32_t)(key * KSD + c16 * 4) * 4, kv + gr);
            cp_async16(smem_base + (uint32_t)(64 * KSD + key * VSD + c16 * 4) * 4, kv + gr + D_MODEL);
        }
        CP_COMMIT();
    }

    float o[8][4];
    #pragma unroll
    for (int nt = 0; nt < 8; nt++)
        #pragma unroll
        for (int i = 0; i < 4; i++) o[nt][i] = 0.f;
    float mrow0 = -1e30f, mrow1 = -1e30f, lrow0 = 0.f, lrow1 = 0.f;

    const int NT = N_TOK / 64;
    for (int t = 0; t < NT; t++) {
        __syncthreads();   // everyone done reading buf[(t+1)&1] from iteration t-1

        if (t + 1 < NT) {
            uint32_t boff = (uint32_t)(((t + 1) & 1) * KVBUF);
            #pragma unroll
            for (int r = 0; r < 4; r++) {
                int e   = tid + 256 * r;
                int key = e >> 4;
                int c16 = e & 15;
                size_t gr = (size_t)((t + 1) * 64 + key) * KV_DIM + hbase + c16 * 4;
                cp_async16(smem_base + (boff + key * KSD + c16 * 4) * 4, kv + gr);
                cp_async16(smem_base + (boff + 64 * KSD + key * VSD + c16 * 4) * 4, kv + gr + D_MODEL);
            }
            CP_COMMIT();
            CP_WAIT(1);
        } else {
            CP_WAIT(0);
        }
        __syncthreads();   // buf[t&1] visible to all

        const uint32_t* Ks = sm + (t & 1) * KVBUF;
        const uint32_t* Vs = Ks + 64 * KSD;

        // ---- S = Q K^T ----
        float s[8][4];
        #pragma unroll
        for (int nt = 0; nt < 8; nt++)
            #pragma unroll
            for (int i = 0; i < 4; i++) s[nt][i] = 0.f;

        #pragma unroll
        for (int kb = 0; kb < 8; kb++) {
            const uint32_t* krow = &Ks[g * KSD + kb * 8 + q];
            #pragma unroll
            for (int nt = 0; nt < 8; nt++) {
                uint32_t bf[2];
                bf[0] = krow[(nt * 8) * KSD];
                bf[1] = krow[(nt * 8) * KSD + 4];
                mma_tf32(s[nt], qf[kb], bf);
            }
        }

        // ---- online softmax (fragment layout) ----
        float mx0 = -1e30f, mx1 = -1e30f;
        #pragma unroll
        for (int nt = 0; nt < 8; nt++) {
            mx0 = fmaxf(mx0, fmaxf(s[nt][0], s[nt][1]));
            mx1 = fmaxf(mx1, fmaxf(s[nt][2], s[nt][3]));
        }
        mx0 = fmaxf(mx0, __shfl_xor_sync(0xffffffffu, mx0, 1));
        mx0 = fmaxf(mx0, __shfl_xor_sync(0xffffffffu, mx0, 2));
        mx1 = fmaxf(mx1, __shfl_xor_sync(0xffffffffu, mx1, 1));
        mx1 = fmaxf(mx1, __shfl_xor_sync(0xffffffffu, mx1, 2));

        float mn0 = fmaxf(mrow0, mx0), mn1 = fmaxf(mrow1, mx1);
        float cor0 = __expf(mrow0 - mn0), cor1 = __expf(mrow1 - mn1);
        float sum0 = 0.f, sum1 = 0.f;

        #pragma unroll
        for (int nt = 0; nt < 8; nt++) {
            s[nt][0] = __expf(s[nt][0] - mn0);
            s[nt][1] = __expf(s[nt][1] - mn0);
            s[nt][2] = __expf(s[nt][2] - mn1);
            s[nt][3] = __expf(s[nt][3] - mn1);
            sum0 += s[nt][0] + s[nt][1];
            sum1 += s[nt][2] + s[nt][3];
        }
        sum0 += __shfl_xor_sync(0xffffffffu, sum0, 1);
        sum0 += __shfl_xor_sync(0xffffffffu, sum0, 2);
        sum1 += __shfl_xor_sync(0xffffffffu, sum1, 1);
        sum1 += __shfl_xor_sync(0xffffffffu, sum1, 2);

        lrow0 = lrow0 * cor0 + sum0;
        lrow1 = lrow1 * cor1 + sum1;
        mrow0 = mn0;
        mrow1 = mn1;
        #pragma unroll
        for (int nt = 0; nt < 8; nt++) {
            o[nt][0] *= cor0; o[nt][1] *= cor0;
            o[nt][2] *= cor1; o[nt][3] *= cor1;
        }

        // ---- O += P V : P fragments via shuffles, rna-rounded to tf32 ----
        const int l0 = g * 4 + (q >> 1);   // src lane for col group c=q
        const int l1 = l0 + 2;             // src lane for col group c=q+4
        const bool odd = (q & 1);
        #pragma unroll
        for (int kb = 0; kb < 8; kb++) {
            float t0  = __shfl_sync(0xffffffffu, s[kb][0], l0);
            float t1  = __shfl_sync(0xffffffffu, s[kb][1], l0);
            float t2  = __shfl_sync(0xffffffffu, s[kb][2], l0);
            float t3  = __shfl_sync(0xffffffffu, s[kb][3], l0);
            float u0  = __shfl_sync(0xffffffffu, s[kb][0], l1);
            float u1  = __shfl_sync(0xffffffffu, s[kb][1], l1);
            float u2  = __shfl_sync(0xffffffffu, s[kb][2], l1);
            float u3  = __shfl_sync(0xffffffffu, s[kb][3], l1);
            uint32_t pa[4];
            pa[0] = f2tf32(odd ? t1 : t0);   // (row g,   k=q)
            pa[1] = f2tf32(odd ? t3 : t2);   // (row g+8, k=q)
            pa[2] = f2tf32(odd ? u1 : u0);   // (row g,   k=q+4)
            pa[3] = f2tf32(odd ? u3 : u2);   // (row g+8, k=q+4)

            const uint32_t* vrow = &Vs[(kb * 8 + q) * VSD + g];
            #pragma unroll
            for (int nt = 0; nt < 8; nt++) {
                uint32_t vf[2];
                vf[0] = vrow[nt * 8];
                vf[1] = vrow[4 * VSD + nt * 8];
                mma_tf32(o[nt], pa, vf);
            }
        }
    }

    // ---- epilogue ----
    float inv0 = 1.0f / lrow0, inv1 = 1.0f / lrow1;
    #pragma unroll
    for (int nt = 0; nt < 8; nt++) {
        int col = hbase + nt * 8 + 2 * q;
        *(float2*)&ao[(size_t)(qbase + r0) * D_MODEL + col] =
            make_float2(o[nt][0] * inv0, o[nt][1] * inv0);
        *(float2*)&ao[(size_t)(qbase + r0 + 8) * D_MODEL + col] =
            make_float2(o[nt][2] * inv1, o[nt][3] * inv1);
    }
}

// ---------------------------------------------------------------------------
extern "C" void kernel_launch(void* const* d_in, const int* in_sizes, int n_in,
                              void* d_out, int out_size)
{
    (void)in_sizes; (void)n_in; (void)out_size;
    const float* q     = (const float*)d_in[0];
    const float* gamma = (const float*)d_in[1];
    const float* beta  = (const float*)d_in[2];
    const float* Wq    = (const float*)d_in[3];
    const float* Wkv   = (const float*)d_in[4];
    const float* Wo    = (const float*)d_in[5];
    float* out = (float*)d_out;

    float *x, *qp, *kvb, *ao;
    cudaGetSymbolAddress((void**)&x,   g_x);
    cudaGetSymbolAddress((void**)&qp,  g_qp);
    cudaGetSymbolAddress((void**)&kvb, g_kv);
    cudaGetSymbolAddress((void**)&ao,  g_ao);

    cudaFuncSetAttribute(attn_tf32_kernel,
                         cudaFuncAttributeMaxDynamicSharedMemorySize, ATTN_SMEM_BYTES);

    ln_kernel<<<N_TOK, 256>>>(q, gamma, beta, x);

    gemm_bf16x3_kernel<<<dim3(D_MODEL/128, N_TOK/128), 256>>>(x, Wq,  qp,  N_TOK, D_MODEL, D_MODEL, 0);
    gemm_bf16x3_kernel<<<dim3(KV_DIM/128,  N_TOK/128), 256>>>(x, Wkv, kvb, N_TOK, KV_DIM,  D_MODEL, 1);

    attn_tf32_kernel<<<dim3(N_TOK/128, N_HEADS), 256, ATTN_SMEM_BYTES>>>(qp, kvb, ao);

    gemm_bf16x3_kernel<<<dim3(D_MODEL/128, N_TOK/128), 256>>>(ao, Wo, out, N_TOK, D_MODEL, D_MODEL, 0);
}

// round 8
// speedup vs baseline: 3.2117x; 1.0193x over previous
#include <cuda_runtime.h>
#include <cuda_bf16.h>
#include <stdint.h>
#include <math.h>

#define N_TOK   4096
#define D_MODEL 1024
#define N_HEADS 16
#define HD      64
#define KV_DIM  2048

// ---------------- scratch (device globals; no allocation allowed) ----------
__device__ float g_x [N_TOK * D_MODEL];   // layernorm output
__device__ float g_qp[N_TOK * D_MODEL];   // q projection  [n, h*64+d]
__device__ float g_kv[N_TOK * KV_DIM];    // kv projection [n, 2048] (tf32-rounded)
__device__ float g_ao[N_TOK * D_MODEL];   // attention output [n, h*64+d]

// ---------------------------------------------------------------------------
// helpers
// ---------------------------------------------------------------------------
__device__ __forceinline__ uint32_t f2tf32(float f) {
    uint32_t r;
    asm("cvt.rna.tf32.f32 %0, %1;" : "=r"(r) : "f"(f));
    return r;
}

__device__ __forceinline__ void mma_tf32(float c[4], const uint32_t a[4], const uint32_t b[2]) {
    asm volatile(
        "mma.sync.aligned.m16n8k8.row.col.f32.tf32.tf32.f32 "
        "{%0,%1,%2,%3}, {%4,%5,%6,%7}, {%8,%9}, {%0,%1,%2,%3};"
        : "+f"(c[0]), "+f"(c[1]), "+f"(c[2]), "+f"(c[3])
        : "r"(a[0]), "r"(a[1]), "r"(a[2]), "r"(a[3]), "r"(b[0]), "r"(b[1]));
}

__device__ __forceinline__ void mma_bf16(float c[4], const uint32_t a[4], const uint32_t b[2]) {
    asm volatile(
        "mma.sync.aligned.m16n8k16.row.col.f32.bf16.bf16.f32 "
        "{%0,%1,%2,%3}, {%4,%5,%6,%7}, {%8,%9}, {%0,%1,%2,%3};"
        : "+f"(c[0]), "+f"(c[1]), "+f"(c[2]), "+f"(c[3])
        : "r"(a[0]), "r"(a[1]), "r"(a[2]), "r"(a[3]), "r"(b[0]), "r"(b[1]));
}

__device__ __forceinline__ uint32_t pack_bf16(__nv_bfloat16 lo, __nv_bfloat16 hi) {
    __nv_bfloat162 t;
    t.x = lo; t.y = hi;
    return *reinterpret_cast<uint32_t*>(&t);
}

__device__ __forceinline__ void cp_async16(uint32_t saddr, const void* gaddr) {
    asm volatile("cp.async.cg.shared.global [%0], [%1], 16;\n" :: "r"(saddr), "l"(gaddr));
}
#define CP_COMMIT() asm volatile("cp.async.commit_group;\n" ::: "memory")
#define CP_WAIT(n)  asm volatile("cp.async.wait_group %0;\n" :: "n"(n) : "memory")

// ---------------------------------------------------------------------------
// LayerNorm
// ---------------------------------------------------------------------------
__device__ __forceinline__ float block_allreduce(float v) {
    __shared__ float red[8];
    __shared__ float bc;
    #pragma unroll
    for (int m = 16; m >= 1; m >>= 1) v += __shfl_xor_sync(0xffffffffu, v, m);
    if ((threadIdx.x & 31) == 0) red[threadIdx.x >> 5] = v;
    __syncthreads();
    if (threadIdx.x == 0) {
        float t = 0.f;
        #pragma unroll
        for (int i = 0; i < 8; i++) t += red[i];
        bc = t;
    }
    __syncthreads();
    float r = bc;
    __syncthreads();
    return r;
}

__global__ __launch_bounds__(256) void ln_kernel(
    const float* __restrict__ q, const float* __restrict__ gamma,
    const float* __restrict__ beta, float* __restrict__ x)
{
    int row = blockIdx.x;
    int tid = threadIdx.x;
    const float4 v = ((const float4*)(q + (size_t)row * D_MODEL))[tid];

    float s = v.x + v.y + v.z + v.w;
    float mu = block_allreduce(s) * (1.0f / D_MODEL);

    float dx = v.x - mu, dy = v.y - mu, dz = v.z - mu, dw = v.w - mu;
    float var = block_allreduce(dx*dx + dy*dy + dz*dz + dw*dw) * (1.0f / D_MODEL);
    float rstd = rsqrtf(var + 1e-5f);

    const float4 g = ((const float4*)gamma)[tid];
    const float4 b = ((const float4*)beta)[tid];
    float4 o;
    o.x = dx * rstd * g.x + b.x;
    o.y = dy * rstd * g.y + b.y;
    o.z = dz * rstd * g.z + b.z;
    o.w = dw * rstd * g.w + b.w;
    ((float4*)(x + (size_t)row * D_MODEL))[tid] = o;
}

// ---------------------------------------------------------------------------
// GEMM (3xBF16, register-pipelined): C[M,N] = A[M,K] @ B[N,K]^T
// round_out != 0 -> store rna-tf32-rounded fp32 (for attention K/V consumer).
// ---------------------------------------------------------------------------
#define WS 12

__global__ __launch_bounds__(256) void gemm_bf16x3_kernel(
    const float* __restrict__ A, const float* __restrict__ B,
    float* __restrict__ C, int M, int N, int K, int round_out)
{
    __shared__ uint32_t Ah[128 * WS], Al[128 * WS];
    __shared__ uint32_t Bh[128 * WS], Bl[128 * WS];

    const int tid  = threadIdx.x;
    const int lane = tid & 31;
    const int warp = tid >> 5;
    const int wm   = (warp >> 1) * 32;
    const int wn   = (warp & 1) * 64;
    const int g    = lane >> 2;
    const int q    = lane & 3;
    const int brow = blockIdx.y * 128;
    const int bcol = blockIdx.x * 128;

    const int row0 = tid >> 2;            // 0..63
    const int row1 = row0 + 64;
    const int c4   = (tid & 3) * 4;       // first float (of 4) in the 16-k row
    const int w0   = (tid & 3) * 2;       // first packed word

    float acc[2][8][4];
    #pragma unroll
    for (int mt = 0; mt < 2; mt++)
        #pragma unroll
        for (int nt = 0; nt < 8; nt++)
            #pragma unroll
            for (int i = 0; i < 4; i++) acc[mt][nt][i] = 0.f;

    // prologue: prefetch k-tile 0
    float4 va0 = *(const float4*)&A[(size_t)(brow + row0) * K + c4];
    float4 va1 = *(const float4*)&A[(size_t)(brow + row1) * K + c4];
    float4 vb0 = *(const float4*)&B[(size_t)(bcol + row0) * K + c4];
    float4 vb1 = *(const float4*)&B[(size_t)(bcol + row1) * K + c4];

    for (int k0 = 0; k0 < K; k0 += 16) {
        __syncthreads();
        {
            #define SPLIT_STORE(SH, SL, ROW, V)                                         \
            {                                                                            \
                __nv_bfloat16 h0 = __float2bfloat16_rn(V.x);                             \
                __nv_bfloat16 h1 = __float2bfloat16_rn(V.y);                             \
                __nv_bfloat16 h2 = __float2bfloat16_rn(V.z);                             \
                __nv_bfloat16 h3 = __float2bfloat16_rn(V.w);                             \
                __nv_bfloat16 l0 = __float2bfloat16_rn(V.x - __bfloat162float(h0));      \
                __nv_bfloat16 l1 = __float2bfloat16_rn(V.y - __bfloat162float(h1));      \
                __nv_bfloat16 l2 = __float2bfloat16_rn(V.z - __bfloat162float(h2));      \
                __nv_bfloat16 l3 = __float2bfloat16_rn(V.w - __bfloat162float(h3));      \
                *(uint2*)&SH[(ROW) * WS + w0] =                                          \
                    make_uint2(pack_bf16(h0, h1), pack_bf16(h2, h3));                    \
                *(uint2*)&SL[(ROW) * WS + w0] =                                          \
                    make_uint2(pack_bf16(l0, l1), pack_bf16(l2, l3));                    \
            }
            SPLIT_STORE(Ah, Al, row0, va0);
            SPLIT_STORE(Ah, Al, row1, va1);
            SPLIT_STORE(Bh, Bl, row0, vb0);
            SPLIT_STORE(Bh, Bl, row1, vb1);
            #undef SPLIT_STORE
        }
        __syncthreads();

        if (k0 + 16 < K) {   // prefetch next tile (overlaps with MMAs below)
            va0 = *(const float4*)&A[(size_t)(brow + row0) * K + k0 + 16 + c4];
            va1 = *(const float4*)&A[(size_t)(brow + row1) * K + k0 + 16 + c4];
            vb0 = *(const float4*)&B[(size_t)(bcol + row0) * K + k0 + 16 + c4];
            vb1 = *(const float4*)&B[(size_t)(bcol + row1) * K + k0 + 16 + c4];
        }

        uint32_t ah[2][4], al[2][4], bh[8][2], bl[8][2];
        #pragma unroll
        for (int mt = 0; mt < 2; mt++) {
            int r0 = wm + mt * 16 + g;
            ah[mt][0] = Ah[r0       * WS + q];
            ah[mt][1] = Ah[(r0 + 8) * WS + q];
            ah[mt][2] = Ah[r0       * WS + q + 4];
            ah[mt][3] = Ah[(r0 + 8) * WS + q + 4];
            al[mt][0] = Al[r0       * WS + q];
            al[mt][1] = Al[(r0 + 8) * WS + q];
            al[mt][2] = Al[r0       * WS + q + 4];
            al[mt][3] = Al[(r0 + 8) * WS + q + 4];
        }
        #pragma unroll
        for (int nt = 0; nt < 8; nt++) {
            int n0 = wn + nt * 8 + g;
            bh[nt][0] = Bh[n0 * WS + q];
            bh[nt][1] = Bh[n0 * WS + q + 4];
            bl[nt][0] = Bl[n0 * WS + q];
            bl[nt][1] = Bl[n0 * WS + q + 4];
        }
        #pragma unroll
        for (int mt = 0; mt < 2; mt++)
            #pragma unroll
            for (int nt = 0; nt < 8; nt++)
                mma_bf16(acc[mt][nt], ah[mt], bh[nt]);
        #pragma unroll
        for (int mt = 0; mt < 2; mt++)
            #pragma unroll
            for (int nt = 0; nt < 8; nt++)
                mma_bf16(acc[mt][nt], al[mt], bh[nt]);
        #pragma unroll
        for (int mt = 0; mt < 2; mt++)
            #pragma unroll
            for (int nt = 0; nt < 8; nt++)
                mma_bf16(acc[mt][nt], ah[mt], bl[nt]);
    }

    if (round_out) {
        #pragma unroll
        for (int mt = 0; mt < 2; mt++)
            #pragma unroll
            for (int nt = 0; nt < 8; nt++)
                #pragma unroll
                for (int i = 0; i < 4; i++)
                    acc[mt][nt][i] = __uint_as_float(f2tf32(acc[mt][nt][i]));
    }

    #pragma unroll
    for (int mt = 0; mt < 2; mt++) {
        int r0 = brow + wm + mt * 16 + g;
        #pragma unroll
        for (int nt = 0; nt < 8; nt++) {
            int cc = bcol + wn + nt * 8 + 2 * q;
            *(float2*)&C[(size_t)r0 * N + cc]       = make_float2(acc[mt][nt][0], acc[mt][nt][1]);
            *(float2*)&C[(size_t)(r0 + 8) * N + cc] = make_float2(acc[mt][nt][2], acc[mt][nt][3]);
        }
    }
}

// ---------------------------------------------------------------------------
// Flash attention, tf32 mma, 3-stage cp.async ring (loads 2 tiles ahead),
// ONE barrier per tile. K/V pre-rounded to tf32 by the Wkv GEMM epilogue.
// P rna-rounded in registers, passed S->A fragment via warp shuffles.
// Block = 256 thr (8 warps); warp w owns query rows 16w..16w+15; KV tile = 64.
// ---------------------------------------------------------------------------
#define QS  68
#define KSD 68
#define VSD 72
#define NSTAGE 3
#define KVBUF (64 * KSD + 64 * VSD)                 // 8960 words per stage
#define ATTN_SMEM_BYTES (NSTAGE * KVBUF * 4)        // 107520 B

__global__ __launch_bounds__(256) void attn_tf32_kernel(
    const float* __restrict__ qp, const float* __restrict__ kv,
    float* __restrict__ ao)
{
    extern __shared__ uint32_t sm[];

    const int tid   = threadIdx.x;
    const int lane  = tid & 31;
    const int warp  = tid >> 5;
    const int g     = lane >> 2;
    const int q     = lane & 3;
    const int qbase = blockIdx.x * 128;
    const int hbase = blockIdx.y * HD;
    const int r0    = warp * 16 + g;

    // ---- stage Q (scaled, rna tf32) into sm and preload frags ----
    #pragma unroll
    for (int r = 0; r < 8; r++) {
        int e   = tid + 256 * r;
        int row = e >> 4;
        int d4  = (e & 15) * 4;
        float4 v = *(const float4*)&qp[(size_t)(qbase + row) * D_MODEL + hbase + d4];
        sm[row * QS + d4 + 0] = f2tf32(v.x * 0.125f);
        sm[row * QS + d4 + 1] = f2tf32(v.y * 0.125f);
        sm[row * QS + d4 + 2] = f2tf32(v.z * 0.125f);
        sm[row * QS + d4 + 3] = f2tf32(v.w * 0.125f);
    }
    __syncthreads();

    uint32_t qf[8][4];
    #pragma unroll
    for (int kb = 0; kb < 8; kb++) {
        qf[kb][0] = sm[r0       * QS + kb * 8 + q];
        qf[kb][1] = sm[(r0 + 8) * QS + kb * 8 + q];
        qf[kb][2] = sm[r0       * QS + kb * 8 + q + 4];
        qf[kb][3] = sm[(r0 + 8) * QS + kb * 8 + q + 4];
    }
    __syncthreads();   // Q reads done; smem becomes the K/V 3-stage ring

    const uint32_t smem_base = (uint32_t)__cvta_generic_to_shared(sm);

    // per-thread fixed chunk coordinates for the cp.async of one tile
    // (4 iterations of: key = (tid+256r)>>4, c16 = (tid+256r)&15)

    // ---- prologue: prefetch tiles 0 and 1 into stages 0,1 ----
    #pragma unroll
    for (int pre = 0; pre < 2; pre++) {
        uint32_t boff = (uint32_t)(pre * KVBUF);
        #pragma unroll
        for (int r = 0; r < 4; r++) {
            int e   = tid + 256 * r;
            int key = e >> 4;
            int c16 = e & 15;
            size_t gr = (size_t)(pre * 64 + key) * KV_DIM + hbase + c16 * 4;
            cp_async16(smem_base + (boff + key * KSD + c16 * 4) * 4, kv + gr);
            cp_async16(smem_base + (boff + 64 * KSD + key * VSD + c16 * 4) * 4, kv + gr + D_MODEL);
        }
        CP_COMMIT();
    }

    float o[8][4];
    #pragma unroll
    for (int nt = 0; nt < 8; nt++)
        #pragma unroll
        for (int i = 0; i < 4; i++) o[nt][i] = 0.f;
    float mrow0 = -1e30f, mrow1 = -1e30f, lrow0 = 0.f, lrow1 = 0.f;

    const int NT = N_TOK / 64;
    int stage = 0;   // ring stage holding tile t

    for (int t = 0; t < NT; t++) {
        if (t == NT - 1) { CP_WAIT(0); } else { CP_WAIT(1); }
        __syncthreads();   // tile t visible; tile t-1 reads drained (its stage is reused below)

        // prefetch tile t+2 into the stage just freed (holds t-1's data)
        if (t + 2 < NT) {
            int pstage = stage + 2; if (pstage >= NSTAGE) pstage -= NSTAGE;
            uint32_t boff = (uint32_t)(pstage * KVBUF);
            #pragma unroll
            for (int r = 0; r < 4; r++) {
                int e   = tid + 256 * r;
                int key = e >> 4;
                int c16 = e & 15;
                size_t gr = (size_t)((t + 2) * 64 + key) * KV_DIM + hbase + c16 * 4;
                cp_async16(smem_base + (boff + key * KSD + c16 * 4) * 4, kv + gr);
                cp_async16(smem_base + (boff + 64 * KSD + key * VSD + c16 * 4) * 4, kv + gr + D_MODEL);
            }
            CP_COMMIT();
        }

        const uint32_t* Ks = sm + stage * KVBUF;
        const uint32_t* Vs = Ks + 64 * KSD;

        // ---- S = Q K^T ----
        float s[8][4];
        #pragma unroll
        for (int nt = 0; nt < 8; nt++)
            #pragma unroll
            for (int i = 0; i < 4; i++) s[nt][i] = 0.f;

        #pragma unroll
        for (int kb = 0; kb < 8; kb++) {
            const uint32_t* krow = &Ks[g * KSD + kb * 8 + q];
            #pragma unroll
            for (int nt = 0; nt < 8; nt++) {
                uint32_t bf[2];
                bf[0] = krow[(nt * 8) * KSD];
                bf[1] = krow[(nt * 8) * KSD + 4];
                mma_tf32(s[nt], qf[kb], bf);
            }
        }

        // ---- online softmax (fragment layout) ----
        float mx0 = -1e30f, mx1 = -1e30f;
        #pragma unroll
        for (int nt = 0; nt < 8; nt++) {
            mx0 = fmaxf(mx0, fmaxf(s[nt][0], s[nt][1]));
            mx1 = fmaxf(mx1, fmaxf(s[nt][2], s[nt][3]));
        }
        mx0 = fmaxf(mx0, __shfl_xor_sync(0xffffffffu, mx0, 1));
        mx0 = fmaxf(mx0, __shfl_xor_sync(0xffffffffu, mx0, 2));
        mx1 = fmaxf(mx1, __shfl_xor_sync(0xffffffffu, mx1, 1));
        mx1 = fmaxf(mx1, __shfl_xor_sync(0xffffffffu, mx1, 2));

        float mn0 = fmaxf(mrow0, mx0), mn1 = fmaxf(mrow1, mx1);
        float cor0 = __expf(mrow0 - mn0), cor1 = __expf(mrow1 - mn1);
        float sum0 = 0.f, sum1 = 0.f;

        #pragma unroll
        for (int nt = 0; nt < 8; nt++) {
            s[nt][0] = __expf(s[nt][0] - mn0);
            s[nt][1] = __expf(s[nt][1] - mn0);
            s[nt][2] = __expf(s[nt][2] - mn1);
            s[nt][3] = __expf(s[nt][3] - mn1);
            sum0 += s[nt][0] + s[nt][1];
            sum1 += s[nt][2] + s[nt][3];
        }
        sum0 += __shfl_xor_sync(0xffffffffu, sum0, 1);
        sum0 += __shfl_xor_sync(0xffffffffu, sum0, 2);
        sum1 += __shfl_xor_sync(0xffffffffu, sum1, 1);
        sum1 += __shfl_xor_sync(0xffffffffu, sum1, 2);

        lrow0 = lrow0 * cor0 + sum0;
        lrow1 = lrow1 * cor1 + sum1;
        mrow0 = mn0;
        mrow1 = mn1;
        #pragma unroll
        for (int nt = 0; nt < 8; nt++) {
            o[nt][0] *= cor0; o[nt][1] *= cor0;
            o[nt][2] *= cor1; o[nt][3] *= cor1;
        }

        // ---- O += P V : P fragments via shuffles, rna-rounded to tf32 ----
        const int l0 = g * 4 + (q >> 1);
        const int l1 = l0 + 2;
        const bool odd = (q & 1);
        #pragma unroll
        for (int kb = 0; kb < 8; kb++) {
            float t0  = __shfl_sync(0xffffffffu, s[kb][0], l0);
            float t1  = __shfl_sync(0xffffffffu, s[kb][1], l0);
            float t2  = __shfl_sync(0xffffffffu, s[kb][2], l0);
            float t3  = __shfl_sync(0xffffffffu, s[kb][3], l0);
            float u0  = __shfl_sync(0xffffffffu, s[kb][0], l1);
            float u1  = __shfl_sync(0xffffffffu, s[kb][1], l1);
            float u2  = __shfl_sync(0xffffffffu, s[kb][2], l1);
            float u3  = __shfl_sync(0xffffffffu, s[kb][3], l1);
            uint32_t pa[4];
            pa[0] = f2tf32(odd ? t1 : t0);
            pa[1] = f2tf32(odd ? t3 : t2);
            pa[2] = f2tf32(odd ? u1 : u0);
            pa[3] = f2tf32(odd ? u3 : u2);

            const uint32_t* vrow = &Vs[(kb * 8 + q) * VSD + g];
            #pragma unroll
            for (int nt = 0; nt < 8; nt++) {
                uint32_t vf[2];
                vf[0] = vrow[nt * 8];
                vf[1] = vrow[4 * VSD + nt * 8];
                mma_tf32(o[nt], pa, vf);
            }
        }

        stage = stage + 1; if (stage >= NSTAGE) stage = 0;
    }

    // ---- epilogue ----
    float inv0 = 1.0f / lrow0, inv1 = 1.0f / lrow1;
    #pragma unroll
    for (int nt = 0; nt < 8; nt++) {
        int col = hbase + nt * 8 + 2 * q;
        *(float2*)&ao[(size_t)(qbase + r0) * D_MODEL + col] =
            make_float2(o[nt][0] * inv0, o[nt][1] * inv0);
        *(float2*)&ao[(size_t)(qbase + r0 + 8) * D_MODEL + col] =
            make_float2(o[nt][2] * inv1, o[nt][3] * inv1);
    }
}

// ---------------------------------------------------------------------------
extern "C" void kernel_launch(void* const* d_in, const int* in_sizes, int n_in,
                              void* d_out, int out_size)
{
    (void)in_sizes; (void)n_in; (void)out_size;
    const float* q     = (const float*)d_in[0];
    const float* gamma = (const float*)d_in[1];
    const float* beta  = (const float*)d_in[2];
    const float* Wq    = (const float*)d_in[3];
    const float* Wkv   = (const float*)d_in[4];
    const float* Wo    = (const float*)d_in[5];
    float* out = (float*)d_out;

    float *x, *qp, *kvb, *ao;
    cudaGetSymbolAddress((void**)&x,   g_x);
    cudaGetSymbolAddress((void**)&qp,  g_qp);
    cudaGetSymbolAddress((void**)&kvb, g_kv);
    cudaGetSymbolAddress((void**)&ao,  g_ao);

    cudaFuncSetAttribute(attn_tf32_kernel,
                         cudaFuncAttributeMaxDynamicSharedMemorySize, ATTN_SMEM_BYTES);

    ln_kernel<<<N_TOK, 256>>>(q, gamma, beta, x);

    gemm_bf16x3_kernel<<<dim3(D_MODEL/128, N_TOK/128), 256>>>(x, Wq,  qp,  N_TOK, D_MODEL, D_MODEL, 0);
    gemm_bf16x3_kernel<<<dim3(KV_DIM/128,  N_TOK/128), 256>>>(x, Wkv, kvb, N_TOK, KV_DIM,  D_MODEL, 1);

    attn_tf32_kernel<<<dim3(N_TOK/128, N_HEADS), 256, ATTN_SMEM_BYTES>>>(qp, kvb, ao);

    gemm_bf16x3_kernel<<<dim3(D_MODEL/128, N_TOK/128), 256>>>(ao, Wo, out, N_TOK, D_MODEL, D_MODEL, 0);
}